// round 1
// baseline (speedup 1.0000x reference)
#include <cuda_runtime.h>
#include <cstdint>

// ---------------------------------------------------------------------------
// FSNet: emb -> biGRU(2 layer) encoder -> broadcast -> biGRU(2 layer) decoder
//        -> fc head (64x20)  and  reconstruction GEMM (6400x10000x256)
// All fp32.  Packed fma.rn.f32x2 used for all heavy FMA work.
// ---------------------------------------------------------------------------

#define B_    64
#define T_    100
#define H_    128
#define G3H   384            // 3*H
#define BT    (B_*T_)        // 6400
#define VOCAB 10000
#define NCLS  20

// ------------------------------ scratch ------------------------------------
__device__ __align__(16) float g_E   [BT * 128];     // embedded input
__device__ __align__(16) float g_GI  [BT * 768];     // input-gate preacts (both dirs)
__device__ __align__(16) float g_GIc [B_ * 768];     // dec layer0 const gi
__device__ __align__(16) float g_Y0  [BT * 256];     // layer0 outputs (enc then dec)
__device__ __align__(16) float g_REC [BT * 256];     // dec layer1 outputs (rec_seq)
__device__ __align__(16) float g_ench[B_ * 512];
__device__ __align__(16) float g_dech[B_ * 512];
__device__ int g_is32;

// --------------------------- f32x2 helpers ---------------------------------
__device__ __forceinline__ unsigned long long pk2(float x, float y) {
    unsigned long long r;
    asm("mov.b64 %0, {%1, %2};" : "=l"(r)
        : "r"(__float_as_uint(x)), "r"(__float_as_uint(y)));
    return r;
}
__device__ __forceinline__ void upk(unsigned long long v, float& x, float& y) {
    unsigned int a, b;
    asm("mov.b64 {%0, %1}, %2;" : "=r"(a), "=r"(b) : "l"(v));
    x = __uint_as_float(a); y = __uint_as_float(b);
}
__device__ __forceinline__ unsigned long long f2fma(unsigned long long a,
                                                    unsigned long long b,
                                                    unsigned long long c) {
    unsigned long long d;
    asm("fma.rn.f32x2 %0, %1, %2, %3;" : "=l"(d) : "l"(a), "l"(b), "l"(c));
    return d;
}
__device__ __forceinline__ float sigm(float x) { return 1.0f / (1.0f + expf(-x)); }

// ------------------------- dtype detect (int32 vs int64) --------------------
__global__ void detect_k(const unsigned int* p) {
    __shared__ int s;
    if (threadIdx.x == 0) s = 0;
    __syncthreads();
    // if x is int64, the high 32-bit word of every element is 0 (values < 1e4)
    if (p[2 * threadIdx.x + 1] != 0) atomicOr(&s, 1);
    __syncthreads();
    if (threadIdx.x == 0) g_is32 = s;
}

// ------------------------------- embedding ----------------------------------
__global__ void embed_k(const void* xraw, const float* __restrict__ emb) {
    int s = blockIdx.x * blockDim.x + threadIdx.x;   // over 6400*32 float4 units
    if (s >= BT * 32) return;
    int i = s >> 5, t = s & 31;
    long long xi;
    if (g_is32) xi = ((const int*)xraw)[i];
    else        xi = ((const long long*)xraw)[i];
    int r = (int)xi;
    if (r > 9999) r = 9999;
    if (r < 0)    r = 0;
    ((float4*)g_E)[s] = ((const float4*)emb)[r * 32 + t];
}

// ------------------------------ tiled GEMM ----------------------------------
// C[M,N] = A[M,K] @ B[N,K]^T + bias[N].   K % 16 == 0, N % 4 == 0.
#define BM 128
#define BN 128
#define BKt 16

__global__ void __launch_bounds__(256) gemm_bt_k(
    const float* __restrict__ A, const float* __restrict__ Bm,
    const float* __restrict__ bias, float* __restrict__ C,
    int M, int N, int K)
{
    __shared__ __align__(16) float As[BKt][BM + 4];
    __shared__ __align__(16) float Bs[BKt][BN + 4];
    int tid = threadIdx.x;
    int tx = tid & 15, ty = tid >> 4;
    int n0 = blockIdx.x * BN, m0 = blockIdx.y * BM;

    unsigned long long acc[4][8];
#pragma unroll
    for (int i = 0; i < 4; i++)
#pragma unroll
        for (int j = 0; j < 8; j++) acc[i][j] = 0ull;  // +0.0f,+0.0f bit pattern

    for (int kk = 0; kk < K; kk += BKt) {
#pragma unroll
        for (int q = 0; q < 2; q++) {
            int s = tid + q * 256;
            int row = s >> 2, kq = s & 3;
            float4 va = make_float4(0.f, 0.f, 0.f, 0.f);
            int gm = m0 + row;
            if (gm < M) va = *(const float4*)(A + (size_t)gm * K + kk + kq * 4);
            As[kq * 4 + 0][row] = va.x; As[kq * 4 + 1][row] = va.y;
            As[kq * 4 + 2][row] = va.z; As[kq * 4 + 3][row] = va.w;
            float4 vb = make_float4(0.f, 0.f, 0.f, 0.f);
            int gn = n0 + row;
            if (gn < N) vb = *(const float4*)(Bm + (size_t)gn * K + kk + kq * 4);
            Bs[kq * 4 + 0][row] = vb.x; Bs[kq * 4 + 1][row] = vb.y;
            Bs[kq * 4 + 2][row] = vb.z; Bs[kq * 4 + 3][row] = vb.w;
        }
        __syncthreads();
#pragma unroll
        for (int k = 0; k < BKt; k++) {
            const unsigned long long* ap =
                (const unsigned long long*)&As[k][ty * 8];
            unsigned long long a0 = ap[0], a1 = ap[1], a2 = ap[2], a3 = ap[3];
            float4 b0 = *(const float4*)&Bs[k][tx * 8];
            float4 b1 = *(const float4*)&Bs[k][tx * 8 + 4];
            float bv[8] = {b0.x, b0.y, b0.z, b0.w, b1.x, b1.y, b1.z, b1.w};
#pragma unroll
            for (int j = 0; j < 8; j++) {
                unsigned long long bd = pk2(bv[j], bv[j]);
                acc[0][j] = f2fma(a0, bd, acc[0][j]);
                acc[1][j] = f2fma(a1, bd, acc[1][j]);
                acc[2][j] = f2fma(a2, bd, acc[2][j]);
                acc[3][j] = f2fma(a3, bd, acc[3][j]);
            }
        }
        __syncthreads();
    }

    // epilogue
    float bvv[8];
#pragma unroll
    for (int j = 0; j < 8; j++) {
        int gc = n0 + tx * 8 + j;
        bvv[j] = (gc < N) ? bias[gc] : 0.f;
    }
    int gc0 = n0 + tx * 8;
    bool c0ok = (gc0 < N), c1ok = (gc0 + 4 < N);
#pragma unroll
    for (int ip = 0; ip < 4; ip++) {
        float lo[8], hi[8];
#pragma unroll
        for (int j = 0; j < 8; j++) {
            upk(acc[ip][j], lo[j], hi[j]);
            lo[j] += bvv[j]; hi[j] += bvv[j];
        }
        int r0 = m0 + ty * 8 + 2 * ip;
        if (r0 < M) {
            float* cp = C + (size_t)r0 * N + gc0;
            if (c0ok) *(float4*)cp       = make_float4(lo[0], lo[1], lo[2], lo[3]);
            if (c1ok) *(float4*)(cp + 4) = make_float4(lo[4], lo[5], lo[6], lo[7]);
        }
        if (r0 + 1 < M) {
            float* cp = C + (size_t)(r0 + 1) * N + gc0;
            if (c0ok) *(float4*)cp       = make_float4(hi[0], hi[1], hi[2], hi[3]);
            if (c1ok) *(float4*)(cp + 4) = make_float4(hi[4], hi[5], hi[6], hi[7]);
        }
    }
}

// ---------------------------- GRU recurrence --------------------------------
// One block per (batch b, direction d).  384 threads: thread o owns gate
// output o = g*128 + j.  Whh row held in registers (64 packed f32x2).
__global__ void __launch_bounds__(384, 1) recur_k(
    const float* __restrict__ GI,    // [B*T][768] or [B][768] (gi_const)
    const float* __restrict__ Whh,   // [2][384][128]
    const float* __restrict__ bhh,   // [2][384]
    float* __restrict__ Y,           // [B*T][256] or nullptr
    float* __restrict__ Hout,        // [B][512]
    int loff, int gi_const)
{
    int b = blockIdx.x, d = blockIdx.y;
    int o = threadIdx.x;
    int g = o >> 7, j = o & 127;

    __shared__ __align__(16) float sh_h[128];
    __shared__ float rbuf[128];
    __shared__ float zbuf[128];

    unsigned long long w2[64];
    const float2* wrow = (const float2*)(Whh + ((size_t)(d * G3H + o)) * H_);
#pragma unroll
    for (int i = 0; i < 64; i++) {
        float2 v = wrow[i];
        w2[i] = pk2(v.x, v.y);
    }
    float bh = bhh[d * G3H + o];
    if (o < 128) sh_h[o] = 0.f;
    __syncthreads();

    float gi_c = gi_const ? GI[(size_t)b * 768 + d * G3H + o] : 0.f;

    for (int s = 0; s < T_; s++) {
        int t = d ? (T_ - 1 - s) : s;
        float gi = gi_const ? gi_c
                            : GI[((size_t)(b * T_ + t)) * 768 + d * G3H + o];
        unsigned long long acc2 = pk2(bh, 0.f);
        const unsigned long long* h2 = (const unsigned long long*)sh_h;
#pragma unroll
        for (int i = 0; i < 64; i++) acc2 = f2fma(w2[i], h2[i], acc2);
        float pa, pb; upk(acc2, pa, pb);
        float gh = pa + pb;                 // h . Whh[o] + bhh[o]

        if (g == 0)      rbuf[j] = sigm(gi + gh);
        else if (g == 1) zbuf[j] = sigm(gi + gh);
        __syncthreads();
        if (g == 2) {
            float r = rbuf[j];
            float n = tanhf(gi + r * gh);
            float z = zbuf[j];
            float hn = (1.f - z) * n + z * sh_h[j];
            sh_h[j] = hn;
            if (Y) Y[((size_t)(b * T_ + t)) * 256 + d * 128 + j] = hn;
        }
        __syncthreads();
    }
    if (g == 2) Hout[(size_t)b * 512 + loff + d * 128 + j] = sh_h[j];
}

// -------------------------------- fc head -----------------------------------
__global__ void fc_k(const float* __restrict__ ench,
                     const float* __restrict__ dech,
                     const float* __restrict__ W,
                     const float* __restrict__ bias,
                     float* __restrict__ out)
{
    int b = blockIdx.x;
    __shared__ float feat[1024];
    int tid = threadIdx.x;
    for (int i = tid; i < 512; i += 256) {
        feat[i]       = ench[b * 512 + i];
        feat[512 + i] = dech[b * 512 + i];
    }
    __syncthreads();
    int w = tid >> 5, lane = tid & 31;
    for (int c = w; c < NCLS; c += 8) {
        float acc = 0.f;
        for (int k = lane; k < 1024; k += 32)
            acc = fmaf(feat[k], W[c * 1024 + k], acc);
#pragma unroll
        for (int off = 16; off; off >>= 1)
            acc += __shfl_down_sync(0xffffffffu, acc, off);
        if (lane == 0) out[b * NCLS + c] = acc + bias[c];
    }
}

// ------------------------------- launcher -----------------------------------
extern "C" void kernel_launch(void* const* d_in, const int* in_sizes, int n_in,
                              void* d_out, int out_size)
{
    const void*  x    = d_in[0];
    const float* emb  = (const float*)d_in[1];
    const float* eWih0 = (const float*)d_in[2];
    const float* eWhh0 = (const float*)d_in[3];
    const float* ebih0 = (const float*)d_in[4];
    const float* ebhh0 = (const float*)d_in[5];
    const float* eWih1 = (const float*)d_in[6];
    const float* eWhh1 = (const float*)d_in[7];
    const float* ebih1 = (const float*)d_in[8];
    const float* ebhh1 = (const float*)d_in[9];
    const float* dWih0 = (const float*)d_in[10];
    const float* dWhh0 = (const float*)d_in[11];
    const float* dbih0 = (const float*)d_in[12];
    const float* dbhh0 = (const float*)d_in[13];
    const float* dWih1 = (const float*)d_in[14];
    const float* dWhh1 = (const float*)d_in[15];
    const float* dbih1 = (const float*)d_in[16];
    const float* dbhh1 = (const float*)d_in[17];
    const float* fcW   = (const float*)d_in[18];
    const float* fcb   = (const float*)d_in[19];
    const float* recW  = (const float*)d_in[20];
    const float* recb  = (const float*)d_in[21];

    float* out = (float*)d_out;          // [64,20]
    float* rec = out + B_ * NCLS;        // [64,100,10000]

    float *pE, *pGI, *pGIc, *pY0, *pREC, *pench, *pdech;
    cudaGetSymbolAddress((void**)&pE,    g_E);
    cudaGetSymbolAddress((void**)&pGI,   g_GI);
    cudaGetSymbolAddress((void**)&pGIc,  g_GIc);
    cudaGetSymbolAddress((void**)&pY0,   g_Y0);
    cudaGetSymbolAddress((void**)&pREC,  g_REC);
    cudaGetSymbolAddress((void**)&pench, g_ench);
    cudaGetSymbolAddress((void**)&pdech, g_dech);

    detect_k<<<1, 64>>>((const unsigned int*)x);
    embed_k<<<(BT * 32 + 255) / 256, 256>>>(x, emb);

    // encoder layer 0
    gemm_bt_k<<<dim3(6, 50), 256>>>(pE, eWih0, ebih0, pGI, BT, 768, 128);
    recur_k<<<dim3(B_, 2), 384>>>(pGI, eWhh0, ebhh0, pY0, pench, 0, 0);
    // encoder layer 1 (outputs not needed, only final hidden)
    gemm_bt_k<<<dim3(6, 50), 256>>>(pY0, eWih1, ebih1, pGI, BT, 768, 256);
    recur_k<<<dim3(B_, 2), 384>>>(pGI, eWhh1, ebhh1, nullptr, pench, 256, 0);
    // decoder layer 0 (input broadcast over time -> gi constant per step)
    gemm_bt_k<<<dim3(6, 1), 256>>>(pench, dWih0, dbih0, pGIc, B_, 768, 512);
    recur_k<<<dim3(B_, 2), 384>>>(pGIc, dWhh0, dbhh0, pY0, pdech, 0, 1);
    // decoder layer 1 (outputs = rec_seq)
    gemm_bt_k<<<dim3(6, 50), 256>>>(pY0, dWih1, dbih1, pGI, BT, 768, 256);
    recur_k<<<dim3(B_, 2), 384>>>(pGI, dWhh1, dbhh1, pREC, pdech, 256, 0);

    // heads
    fc_k<<<B_, 256>>>(pench, pdech, fcW, fcb, out);
    gemm_bt_k<<<dim3(79, 50), 256>>>(pREC, recW, recb, rec, BT, VOCAB, 256);
}

// round 3
// speedup vs baseline: 2.6487x; 2.6487x over previous
#include <cuda_runtime.h>
#include <cuda_fp16.h>
#include <cstdint>

// ---------------------------------------------------------------------------
// FSNet: emb -> biGRU(2 layer) encoder -> broadcast -> biGRU(2 layer) decoder
//        -> fc head (64x20)  and  reconstruction GEMM (6400x10000x256)
// GRU path fp32 (f32x2 packed FMA). Reconstruction GEMM fp16 HMMA (fp32 acc).
// ---------------------------------------------------------------------------

#define B_    64
#define T_    100
#define H_    128
#define G3H   384            // 3*H
#define BT    (B_*T_)        // 6400
#define VOCAB 10000
#define NCLS  20

// ------------------------------ scratch ------------------------------------
__device__ __align__(16) float  g_E   [BT * 128];     // embedded input
__device__ __align__(16) float  g_GI  [BT * 768];     // input-gate preacts
__device__ __align__(16) float  g_GIc [B_ * 768];     // dec layer0 const gi
__device__ __align__(16) float  g_Y0  [BT * 256];     // layer0 outputs
__device__ __align__(16) __half g_RECh[BT * 256];     // rec_seq in fp16
__device__ __align__(16) __half g_Wh  [VOCAB * 256];  // rec_W in fp16
__device__ __align__(16) float  g_ench[B_ * 512];
__device__ __align__(16) float  g_dech[B_ * 512];
__device__ int g_is32;

// --------------------------- f32x2 helpers ---------------------------------
__device__ __forceinline__ unsigned long long pk2(float x, float y) {
    unsigned long long r;
    asm("mov.b64 %0, {%1, %2};" : "=l"(r)
        : "r"(__float_as_uint(x)), "r"(__float_as_uint(y)));
    return r;
}
__device__ __forceinline__ void upk(unsigned long long v, float& x, float& y) {
    unsigned int a, b;
    asm("mov.b64 {%0, %1}, %2;" : "=r"(a), "=r"(b) : "l"(v));
    x = __uint_as_float(a); y = __uint_as_float(b);
}
__device__ __forceinline__ unsigned long long f2fma(unsigned long long a,
                                                    unsigned long long b,
                                                    unsigned long long c) {
    unsigned long long d;
    asm("fma.rn.f32x2 %0, %1, %2, %3;" : "=l"(d) : "l"(a), "l"(b), "l"(c));
    return d;
}

// ------------------------- fast activations (MUFU) --------------------------
__device__ __forceinline__ float fast_sigm(float x) {
    float e;
    asm("ex2.approx.f32 %0, %1;" : "=f"(e) : "f"(-1.4426950408889634f * x));
    float r;
    asm("rcp.approx.f32 %0, %1;" : "=f"(r) : "f"(1.0f + e));
    return r;
}
__device__ __forceinline__ float fast_tanh(float x) {
    return 2.0f * fast_sigm(2.0f * x) - 1.0f;
}

// ------------------------- dtype detect (int32 vs int64) --------------------
__global__ void detect_k(const unsigned int* p) {
    __shared__ int s;
    if (threadIdx.x == 0) s = 0;
    __syncthreads();
    if (p[2 * threadIdx.x + 1] != 0) atomicOr(&s, 1);
    __syncthreads();
    if (threadIdx.x == 0) g_is32 = s;
}

// ------------------------------- embedding ----------------------------------
__global__ void embed_k(const void* xraw, const float* __restrict__ emb) {
    int s = blockIdx.x * blockDim.x + threadIdx.x;
    if (s >= BT * 32) return;
    int i = s >> 5, t = s & 31;
    long long xi;
    if (g_is32) xi = ((const int*)xraw)[i];
    else        xi = ((const long long*)xraw)[i];
    int r = (int)xi;
    if (r > 9999) r = 9999;
    if (r < 0)    r = 0;
    ((float4*)g_E)[s] = ((const float4*)emb)[r * 32 + t];
}

// -------------------------- fp32 -> fp16 convert ----------------------------
__global__ void cvt_k(const float* __restrict__ src, __half* __restrict__ dst,
                      int n2) {
    int i = blockIdx.x * blockDim.x + threadIdx.x;   // over float2 units
    if (i >= n2) return;
    float2 v = ((const float2*)src)[i];
    ((__half2*)dst)[i] = __floats2half2_rn(v.x, v.y);
}

// ------------------------------ tiled fp32 GEMM -----------------------------
// C[M,N] = A[M,K] @ B[N,K]^T + bias[N].   K % 16 == 0, N % 4 == 0.
#define BM 128
#define BN 128
#define BKt 16

__global__ void __launch_bounds__(256) gemm_bt_k(
    const float* __restrict__ A, const float* __restrict__ Bm,
    const float* __restrict__ bias, float* __restrict__ C,
    int M, int N, int K)
{
    __shared__ __align__(16) float As[BKt][BM + 4];
    __shared__ __align__(16) float Bs[BKt][BN + 4];
    int tid = threadIdx.x;
    int tx = tid & 15, ty = tid >> 4;
    int n0 = blockIdx.x * BN, m0 = blockIdx.y * BM;

    unsigned long long acc[4][8];
#pragma unroll
    for (int i = 0; i < 4; i++)
#pragma unroll
        for (int j = 0; j < 8; j++) acc[i][j] = 0ull;

    for (int kk = 0; kk < K; kk += BKt) {
#pragma unroll
        for (int q = 0; q < 2; q++) {
            int s = tid + q * 256;
            int row = s >> 2, kq = s & 3;
            float4 va = make_float4(0.f, 0.f, 0.f, 0.f);
            int gm = m0 + row;
            if (gm < M) va = *(const float4*)(A + (size_t)gm * K + kk + kq * 4);
            As[kq * 4 + 0][row] = va.x; As[kq * 4 + 1][row] = va.y;
            As[kq * 4 + 2][row] = va.z; As[kq * 4 + 3][row] = va.w;
            float4 vb = make_float4(0.f, 0.f, 0.f, 0.f);
            int gn = n0 + row;
            if (gn < N) vb = *(const float4*)(Bm + (size_t)gn * K + kk + kq * 4);
            Bs[kq * 4 + 0][row] = vb.x; Bs[kq * 4 + 1][row] = vb.y;
            Bs[kq * 4 + 2][row] = vb.z; Bs[kq * 4 + 3][row] = vb.w;
        }
        __syncthreads();
#pragma unroll
        for (int k = 0; k < BKt; k++) {
            const unsigned long long* ap =
                (const unsigned long long*)&As[k][ty * 8];
            unsigned long long a0 = ap[0], a1 = ap[1], a2 = ap[2], a3 = ap[3];
            float4 b0 = *(const float4*)&Bs[k][tx * 8];
            float4 b1 = *(const float4*)&Bs[k][tx * 8 + 4];
            float bv[8] = {b0.x, b0.y, b0.z, b0.w, b1.x, b1.y, b1.z, b1.w};
#pragma unroll
            for (int j = 0; j < 8; j++) {
                unsigned long long bd = pk2(bv[j], bv[j]);
                acc[0][j] = f2fma(a0, bd, acc[0][j]);
                acc[1][j] = f2fma(a1, bd, acc[1][j]);
                acc[2][j] = f2fma(a2, bd, acc[2][j]);
                acc[3][j] = f2fma(a3, bd, acc[3][j]);
            }
        }
        __syncthreads();
    }

    float bvv[8];
#pragma unroll
    for (int j = 0; j < 8; j++) {
        int gc = n0 + tx * 8 + j;
        bvv[j] = (gc < N) ? bias[gc] : 0.f;
    }
    int gc0 = n0 + tx * 8;
    bool c0ok = (gc0 < N), c1ok = (gc0 + 4 < N);
#pragma unroll
    for (int ip = 0; ip < 4; ip++) {
        float lo[8], hi[8];
#pragma unroll
        for (int j = 0; j < 8; j++) {
            upk(acc[ip][j], lo[j], hi[j]);
            lo[j] += bvv[j]; hi[j] += bvv[j];
        }
        int r0 = m0 + ty * 8 + 2 * ip;
        if (r0 < M) {
            float* cp = C + (size_t)r0 * N + gc0;
            if (c0ok) *(float4*)cp       = make_float4(lo[0], lo[1], lo[2], lo[3]);
            if (c1ok) *(float4*)(cp + 4) = make_float4(lo[4], lo[5], lo[6], lo[7]);
        }
        if (r0 + 1 < M) {
            float* cp = C + (size_t)(r0 + 1) * N + gc0;
            if (c0ok) *(float4*)cp       = make_float4(hi[0], hi[1], hi[2], hi[3]);
            if (c1ok) *(float4*)(cp + 4) = make_float4(hi[4], hi[5], hi[6], hi[7]);
        }
    }
}

// ----------------------- fp16 HMMA GEMM (rec head) --------------------------
// C[M,N] = Ah[M,K=256] @ Bh[N,K]^T + bias.  M=6400 (mult of 128), N=10000.
// Block tile 128x64, K-chunk 32, 8 warps (2 M x 4 N), warp tile 64x16.
#define HM 128
#define HN 64
#define HK 32
#define HPAD 40   // smem row stride in halves

__global__ void __launch_bounds__(256) gemm_h_k(
    const __half* __restrict__ A, const __half* __restrict__ Bm,
    const float* __restrict__ bias, float* __restrict__ C,
    int M, int N, int K)
{
    __shared__ __align__(16) __half Ah[HM][HPAD];
    __shared__ __align__(16) __half Bh[HN][HPAD];

    int tid = threadIdx.x;
    int wid = tid >> 5, lane = tid & 31;
    int wm = wid & 1, wn = wid >> 1;          // warp 2x4
    int g = lane >> 2, q = lane & 3;
    int m0 = blockIdx.y * HM, n0 = blockIdx.x * HN;

    float c[4][2][4];
#pragma unroll
    for (int mi = 0; mi < 4; mi++)
#pragma unroll
        for (int ni = 0; ni < 2; ni++)
#pragma unroll
            for (int r = 0; r < 4; r++) c[mi][ni][r] = 0.f;

    for (int kk = 0; kk < K; kk += HK) {
        // A: 128 rows x 32 halves; each thread 16 halves (2 x uint4)
        {
            int row = tid >> 1, seg = (tid & 1) * 16;
            const uint4* src = (const uint4*)(A + (size_t)(m0 + row) * K + kk + seg);
            uint4* dst = (uint4*)&Ah[row][seg];
            dst[0] = src[0];
            dst[1] = src[1];
        }
        // B: 64 rows x 32 halves; each thread 8 halves (1 x uint4), n-guarded
        {
            int row = tid >> 2, seg = (tid & 3) * 8;
            uint4 v = make_uint4(0u, 0u, 0u, 0u);
            int gn = n0 + row;
            if (gn < N) v = *(const uint4*)(Bm + (size_t)gn * K + kk + seg);
            *(uint4*)&Bh[row][seg] = v;
        }
        __syncthreads();

#pragma unroll
        for (int ks = 0; ks < 2; ks++) {
            int kb = ks * 16 + 2 * q;
            unsigned int a[4][4], bfr[2][2];
#pragma unroll
            for (int mi = 0; mi < 4; mi++) {
                int r0 = wm * 64 + mi * 16;
                a[mi][0] = *(const unsigned int*)&Ah[r0 + g][kb];
                a[mi][1] = *(const unsigned int*)&Ah[r0 + g + 8][kb];
                a[mi][2] = *(const unsigned int*)&Ah[r0 + g][kb + 8];
                a[mi][3] = *(const unsigned int*)&Ah[r0 + g + 8][kb + 8];
            }
#pragma unroll
            for (int ni = 0; ni < 2; ni++) {
                int nb = wn * 16 + ni * 8;
                bfr[ni][0] = *(const unsigned int*)&Bh[nb + g][kb];
                bfr[ni][1] = *(const unsigned int*)&Bh[nb + g][kb + 8];
            }
#pragma unroll
            for (int mi = 0; mi < 4; mi++)
#pragma unroll
                for (int ni = 0; ni < 2; ni++) {
                    asm volatile(
                        "mma.sync.aligned.m16n8k16.row.col.f32.f16.f16.f32 "
                        "{%0,%1,%2,%3}, {%4,%5,%6,%7}, {%8,%9}, {%0,%1,%2,%3};\n"
                        : "+f"(c[mi][ni][0]), "+f"(c[mi][ni][1]),
                          "+f"(c[mi][ni][2]), "+f"(c[mi][ni][3])
                        : "r"(a[mi][0]), "r"(a[mi][1]), "r"(a[mi][2]), "r"(a[mi][3]),
                          "r"(bfr[ni][0]), "r"(bfr[ni][1]));
                }
        }
        __syncthreads();
    }

    // epilogue
#pragma unroll
    for (int ni = 0; ni < 2; ni++) {
        int ncol = n0 + wn * 16 + ni * 8 + 2 * q;
        if (ncol >= N) continue;                 // N even, pairs never split
        float b0 = bias[ncol], b1 = bias[ncol + 1];
#pragma unroll
        for (int mi = 0; mi < 4; mi++) {
            int r0 = m0 + wm * 64 + mi * 16 + g;
            float* cp0 = C + (size_t)r0 * N + ncol;
            *(float2*)cp0 = make_float2(c[mi][ni][0] + b0, c[mi][ni][1] + b1);
            float* cp1 = C + (size_t)(r0 + 8) * N + ncol;
            *(float2*)cp1 = make_float2(c[mi][ni][2] + b0, c[mi][ni][3] + b1);
        }
    }
}

// ---------------------------- GRU recurrence --------------------------------
// One block per (batch b, direction d).  384 threads: thread o owns gate
// output o = g*128 + j.  Whh row held in registers (64 packed f32x2).
__global__ void __launch_bounds__(384, 1) recur_k(
    const float* __restrict__ GI,    // [B*T][768] or [B][768] (gi_const)
    const float* __restrict__ Whh,   // [2][384][128]
    const float* __restrict__ bhh,   // [2][384]
    float* __restrict__ Yf,          // fp32 outputs [B*T][256] or nullptr
    __half* __restrict__ Yh,         // fp16 outputs or nullptr
    float* __restrict__ Hout,        // [B][512]
    int loff, int gi_const)
{
    int b = blockIdx.x, d = blockIdx.y;
    int o = threadIdx.x;
    int g = o >> 7, j = o & 127;

    __shared__ __align__(16) float sh_h[128];
    __shared__ float rbuf[128];
    __shared__ float zbuf[128];

    unsigned long long w2[64];
    const float2* wrow = (const float2*)(Whh + ((size_t)(d * G3H + o)) * H_);
#pragma unroll
    for (int i = 0; i < 64; i++) {
        float2 v = wrow[i];
        w2[i] = pk2(v.x, v.y);
    }
    float bh = bhh[d * G3H + o];
    if (o < 128) sh_h[o] = 0.f;
    __syncthreads();

    float gi_c = gi_const ? GI[(size_t)b * 768 + d * G3H + o] : 0.f;

    for (int s = 0; s < T_; s++) {
        int t = d ? (T_ - 1 - s) : s;
        float gi = gi_const ? gi_c
                            : GI[((size_t)(b * T_ + t)) * 768 + d * G3H + o];
        unsigned long long acc0 = pk2(bh, 0.f);
        unsigned long long acc1 = 0ull;
        const float4* h4 = (const float4*)sh_h;
#pragma unroll
        for (int i = 0; i < 16; i++) {
            float4 v0 = h4[2 * i];
            float4 v1 = h4[2 * i + 1];
            acc0 = f2fma(w2[4 * i + 0], pk2(v0.x, v0.y), acc0);
            acc1 = f2fma(w2[4 * i + 1], pk2(v0.z, v0.w), acc1);
            acc0 = f2fma(w2[4 * i + 2], pk2(v1.x, v1.y), acc0);
            acc1 = f2fma(w2[4 * i + 3], pk2(v1.z, v1.w), acc1);
        }
        float pa, pb, pc, pd;
        upk(acc0, pa, pb); upk(acc1, pc, pd);
        float gh = (pa + pc) + (pb + pd);     // h . Whh[o] + bhh[o]

        if (g == 0)      rbuf[j] = fast_sigm(gi + gh);
        else if (g == 1) zbuf[j] = fast_sigm(gi + gh);
        __syncthreads();
        if (g == 2) {
            float r = rbuf[j];
            float n = fast_tanh(gi + r * gh);
            float z = zbuf[j];
            float hn = (1.f - z) * n + z * sh_h[j];
            sh_h[j] = hn;
            int idx = (b * T_ + t) * 256 + d * 128 + j;
            if (Yf) Yf[idx] = hn;
            if (Yh) Yh[idx] = __float2half(hn);
        }
        __syncthreads();
    }
    if (g == 2) Hout[(size_t)b * 512 + loff + d * 128 + j] = sh_h[j];
}

// -------------------------------- fc head -----------------------------------
__global__ void fc_k(const float* __restrict__ ench,
                     const float* __restrict__ dech,
                     const float* __restrict__ W,
                     const float* __restrict__ bias,
                     float* __restrict__ out)
{
    int b = blockIdx.x;
    __shared__ float feat[1024];
    int tid = threadIdx.x;
    for (int i = tid; i < 512; i += 256) {
        feat[i]       = ench[b * 512 + i];
        feat[512 + i] = dech[b * 512 + i];
    }
    __syncthreads();
    int w = tid >> 5, lane = tid & 31;
    for (int c = w; c < NCLS; c += 8) {
        float acc = 0.f;
        for (int k = lane; k < 1024; k += 32)
            acc = fmaf(feat[k], W[c * 1024 + k], acc);
#pragma unroll
        for (int off = 16; off; off >>= 1)
            acc += __shfl_down_sync(0xffffffffu, acc, off);
        if (lane == 0) out[b * NCLS + c] = acc + bias[c];
    }
}

// ------------------------------- launcher -----------------------------------
extern "C" void kernel_launch(void* const* d_in, const int* in_sizes, int n_in,
                              void* d_out, int out_size)
{
    const void*  x    = d_in[0];
    const float* emb  = (const float*)d_in[1];
    const float* eWih0 = (const float*)d_in[2];
    const float* eWhh0 = (const float*)d_in[3];
    const float* ebih0 = (const float*)d_in[4];
    const float* ebhh0 = (const float*)d_in[5];
    const float* eWih1 = (const float*)d_in[6];
    const float* eWhh1 = (const float*)d_in[7];
    const float* ebih1 = (const float*)d_in[8];
    const float* ebhh1 = (const float*)d_in[9];
    const float* dWih0 = (const float*)d_in[10];
    const float* dWhh0 = (const float*)d_in[11];
    const float* dbih0 = (const float*)d_in[12];
    const float* dbhh0 = (const float*)d_in[13];
    const float* dWih1 = (const float*)d_in[14];
    const float* dWhh1 = (const float*)d_in[15];
    const float* dbih1 = (const float*)d_in[16];
    const float* dbhh1 = (const float*)d_in[17];
    const float* fcW   = (const float*)d_in[18];
    const float* fcb   = (const float*)d_in[19];
    const float* recW  = (const float*)d_in[20];
    const float* recb  = (const float*)d_in[21];

    float* out = (float*)d_out;          // [64,20]
    float* rec = out + B_ * NCLS;        // [64,100,10000]

    float *pE, *pGI, *pGIc, *pY0, *pench, *pdech;
    __half *pRECh, *pWh;
    cudaGetSymbolAddress((void**)&pE,    g_E);
    cudaGetSymbolAddress((void**)&pGI,   g_GI);
    cudaGetSymbolAddress((void**)&pGIc,  g_GIc);
    cudaGetSymbolAddress((void**)&pY0,   g_Y0);
    cudaGetSymbolAddress((void**)&pRECh, g_RECh);
    cudaGetSymbolAddress((void**)&pWh,   g_Wh);
    cudaGetSymbolAddress((void**)&pench, g_ench);
    cudaGetSymbolAddress((void**)&pdech, g_dech);

    detect_k<<<1, 64>>>((const unsigned int*)x);
    embed_k<<<(BT * 32 + 255) / 256, 256>>>(x, emb);
    cvt_k<<<(VOCAB * 128 + 255) / 256, 256>>>(recW, pWh, VOCAB * 128);

    // encoder layer 0
    gemm_bt_k<<<dim3(6, 50), 256>>>(pE, eWih0, ebih0, pGI, BT, 768, 128);
    recur_k<<<dim3(B_, 2), 384>>>(pGI, eWhh0, ebhh0, pY0, nullptr, pench, 0, 0);
    // encoder layer 1 (only final hidden needed)
    gemm_bt_k<<<dim3(6, 50), 256>>>(pY0, eWih1, ebih1, pGI, BT, 768, 256);
    recur_k<<<dim3(B_, 2), 384>>>(pGI, eWhh1, ebhh1, nullptr, nullptr, pench, 256, 0);
    // decoder layer 0 (broadcast input -> gi constant per step)
    gemm_bt_k<<<dim3(6, 1), 256>>>(pench, dWih0, dbih0, pGIc, B_, 768, 512);
    recur_k<<<dim3(B_, 2), 384>>>(pGIc, dWhh0, dbhh0, pY0, nullptr, pdech, 0, 1);
    // decoder layer 1 (outputs = rec_seq, written in fp16 for the HMMA GEMM)
    gemm_bt_k<<<dim3(6, 50), 256>>>(pY0, dWih1, dbih1, pGI, BT, 768, 256);
    recur_k<<<dim3(B_, 2), 384>>>(pGI, dWhh1, dbhh1, nullptr, pRECh, pdech, 256, 0);

    // heads
    fc_k<<<B_, 256>>>(pench, pdech, fcW, fcb, out);
    gemm_h_k<<<dim3((VOCAB + HN - 1) / HN, BT / HM), 256>>>(
        pRECh, pWh, recb, rec, BT, VOCAB, 256);
}

// round 4
// speedup vs baseline: 2.8050x; 1.0590x over previous
#include <cuda_runtime.h>
#include <cuda_fp16.h>
#include <cstdint>

// ---------------------------------------------------------------------------
// FSNet: emb -> biGRU(2 layer) encoder -> broadcast -> biGRU(2 layer) decoder
//        -> fc head (64x20)  and  reconstruction GEMM (6400x10000x256)
// GRU path fp32 (f32x2 packed FMA). Reconstruction GEMM fp16 HMMA (fp32 acc)
// with cp.async double buffering + ldmatrix.
// ---------------------------------------------------------------------------

#define B_    64
#define T_    100
#define H_    128
#define G3H   384            // 3*H
#define BT    (B_*T_)        // 6400
#define VOCAB 10000
#define NCLS  20

// ------------------------------ scratch ------------------------------------
__device__ __align__(16) float  g_E   [BT * 128];     // embedded input
__device__ __align__(16) float  g_GI  [BT * 768];     // input-gate preacts
__device__ __align__(16) float  g_GIc [B_ * 768];     // dec layer0 const gi
__device__ __align__(16) float  g_Y0  [BT * 256];     // layer0 outputs
__device__ __align__(16) __half g_RECh[BT * 256];     // rec_seq in fp16
__device__ __align__(16) __half g_Wh  [VOCAB * 256];  // rec_W in fp16
__device__ __align__(16) float  g_ench[B_ * 512];
__device__ __align__(16) float  g_dech[B_ * 512];
__device__ int g_is32;

// --------------------------- helpers ---------------------------------------
__device__ __forceinline__ unsigned long long pk2(float x, float y) {
    unsigned long long r;
    asm("mov.b64 %0, {%1, %2};" : "=l"(r)
        : "r"(__float_as_uint(x)), "r"(__float_as_uint(y)));
    return r;
}
__device__ __forceinline__ void upk(unsigned long long v, float& x, float& y) {
    unsigned int a, b;
    asm("mov.b64 {%0, %1}, %2;" : "=r"(a), "=r"(b) : "l"(v));
    x = __uint_as_float(a); y = __uint_as_float(b);
}
__device__ __forceinline__ unsigned long long f2fma(unsigned long long a,
                                                    unsigned long long b,
                                                    unsigned long long c) {
    unsigned long long d;
    asm("fma.rn.f32x2 %0, %1, %2, %3;" : "=l"(d) : "l"(a), "l"(b), "l"(c));
    return d;
}
__device__ __forceinline__ float fast_sigm(float x) {
    float e;
    asm("ex2.approx.f32 %0, %1;" : "=f"(e) : "f"(-1.4426950408889634f * x));
    float r;
    asm("rcp.approx.f32 %0, %1;" : "=f"(r) : "f"(1.0f + e));
    return r;
}
__device__ __forceinline__ float fast_tanh(float x) {
    return 2.0f * fast_sigm(2.0f * x) - 1.0f;
}
__device__ __forceinline__ uint32_t smaddr(const void* p) {
    return (uint32_t)__cvta_generic_to_shared(p);
}
__device__ __forceinline__ void cp16(uint32_t dst, const void* src) {
    asm volatile("cp.async.cg.shared.global [%0], [%1], 16;"
                 :: "r"(dst), "l"(src));
}

// ------------------------- dtype detect (int32 vs int64) --------------------
__global__ void detect_k(const unsigned int* p) {
    __shared__ int s;
    if (threadIdx.x == 0) s = 0;
    __syncthreads();
    if (p[2 * threadIdx.x + 1] != 0) atomicOr(&s, 1);
    __syncthreads();
    if (threadIdx.x == 0) g_is32 = s;
}

// ------------------------------- embedding ----------------------------------
__global__ void embed_k(const void* xraw, const float* __restrict__ emb) {
    int s = blockIdx.x * blockDim.x + threadIdx.x;
    if (s >= BT * 32) return;
    int i = s >> 5, t = s & 31;
    long long xi;
    if (g_is32) xi = ((const int*)xraw)[i];
    else        xi = ((const long long*)xraw)[i];
    int r = (int)xi;
    if (r > 9999) r = 9999;
    if (r < 0)    r = 0;
    ((float4*)g_E)[s] = ((const float4*)emb)[r * 32 + t];
}

// -------------------------- fp32 -> fp16 convert ----------------------------
__global__ void cvt_k(const float* __restrict__ src, __half* __restrict__ dst,
                      int n2) {
    int i = blockIdx.x * blockDim.x + threadIdx.x;
    if (i >= n2) return;
    float2 v = ((const float2*)src)[i];
    ((__half2*)dst)[i] = __floats2half2_rn(v.x, v.y);
}

// ------------------------------ tiled fp32 GEMM -----------------------------
// C[M,N] = A[M,K] @ B[N,K]^T + bias[N].
#define BM 128
#define BN 128
#define BKt 16

__global__ void __launch_bounds__(256) gemm_bt_k(
    const float* __restrict__ A, const float* __restrict__ Bm,
    const float* __restrict__ bias, float* __restrict__ C,
    int M, int N, int K)
{
    __shared__ __align__(16) float As[BKt][BM + 4];
    __shared__ __align__(16) float Bs[BKt][BN + 4];
    int tid = threadIdx.x;
    int tx = tid & 15, ty = tid >> 4;
    int n0 = blockIdx.x * BN, m0 = blockIdx.y * BM;

    unsigned long long acc[4][8];
#pragma unroll
    for (int i = 0; i < 4; i++)
#pragma unroll
        for (int j = 0; j < 8; j++) acc[i][j] = 0ull;

    for (int kk = 0; kk < K; kk += BKt) {
#pragma unroll
        for (int q = 0; q < 2; q++) {
            int s = tid + q * 256;
            int row = s >> 2, kq = s & 3;
            float4 va = make_float4(0.f, 0.f, 0.f, 0.f);
            int gm = m0 + row;
            if (gm < M) va = *(const float4*)(A + (size_t)gm * K + kk + kq * 4);
            As[kq * 4 + 0][row] = va.x; As[kq * 4 + 1][row] = va.y;
            As[kq * 4 + 2][row] = va.z; As[kq * 4 + 3][row] = va.w;
            float4 vb = make_float4(0.f, 0.f, 0.f, 0.f);
            int gn = n0 + row;
            if (gn < N) vb = *(const float4*)(Bm + (size_t)gn * K + kk + kq * 4);
            Bs[kq * 4 + 0][row] = vb.x; Bs[kq * 4 + 1][row] = vb.y;
            Bs[kq * 4 + 2][row] = vb.z; Bs[kq * 4 + 3][row] = vb.w;
        }
        __syncthreads();
#pragma unroll
        for (int k = 0; k < BKt; k++) {
            const unsigned long long* ap =
                (const unsigned long long*)&As[k][ty * 8];
            unsigned long long a0 = ap[0], a1 = ap[1], a2 = ap[2], a3 = ap[3];
            float4 b0 = *(const float4*)&Bs[k][tx * 8];
            float4 b1 = *(const float4*)&Bs[k][tx * 8 + 4];
            float bv[8] = {b0.x, b0.y, b0.z, b0.w, b1.x, b1.y, b1.z, b1.w};
#pragma unroll
            for (int j = 0; j < 8; j++) {
                unsigned long long bd = pk2(bv[j], bv[j]);
                acc[0][j] = f2fma(a0, bd, acc[0][j]);
                acc[1][j] = f2fma(a1, bd, acc[1][j]);
                acc[2][j] = f2fma(a2, bd, acc[2][j]);
                acc[3][j] = f2fma(a3, bd, acc[3][j]);
            }
        }
        __syncthreads();
    }

    float bvv[8];
#pragma unroll
    for (int j = 0; j < 8; j++) {
        int gc = n0 + tx * 8 + j;
        bvv[j] = (gc < N) ? bias[gc] : 0.f;
    }
    int gc0 = n0 + tx * 8;
    bool c0ok = (gc0 < N), c1ok = (gc0 + 4 < N);
#pragma unroll
    for (int ip = 0; ip < 4; ip++) {
        float lo[8], hi[8];
#pragma unroll
        for (int j = 0; j < 8; j++) {
            upk(acc[ip][j], lo[j], hi[j]);
            lo[j] += bvv[j]; hi[j] += bvv[j];
        }
        int r0 = m0 + ty * 8 + 2 * ip;
        if (r0 < M) {
            float* cp = C + (size_t)r0 * N + gc0;
            if (c0ok) *(float4*)cp       = make_float4(lo[0], lo[1], lo[2], lo[3]);
            if (c1ok) *(float4*)(cp + 4) = make_float4(lo[4], lo[5], lo[6], lo[7]);
        }
        if (r0 + 1 < M) {
            float* cp = C + (size_t)(r0 + 1) * N + gc0;
            if (c0ok) *(float4*)cp       = make_float4(hi[0], hi[1], hi[2], hi[3]);
            if (c1ok) *(float4*)(cp + 4) = make_float4(hi[4], hi[5], hi[6], hi[7]);
        }
    }
}

// ----------------------- fp16 HMMA GEMM (rec head) --------------------------
// C[M=6400,N=10000] = A[M,256] @ B[N,256]^T + bias.
// Block 128x128, K-chunk 32 double-buffered (cp.async), 8 warps 2x4,
// warp tile 64x32, ldmatrix.x4 fragment loads from XOR-swizzled smem.
__global__ void __launch_bounds__(256, 2) gemm_h_k(
    const __half* __restrict__ A, const __half* __restrict__ Bm,
    const float* __restrict__ bias, float* __restrict__ C, int N)
{
    const int K = 256;
    __shared__ __align__(16) __half Asm[2][128 * 32];
    __shared__ __align__(16) __half Bsm[2][128 * 32];

    int tid = threadIdx.x, lane = tid & 31, wid = tid >> 5;
    int wm = wid & 1, wn = wid >> 1;
    int m0 = blockIdx.y * 128, n0 = blockIdx.x * 128;

    float c[4][4][4];
#pragma unroll
    for (int mi = 0; mi < 4; mi++)
#pragma unroll
        for (int ni = 0; ni < 4; ni++)
#pragma unroll
            for (int r = 0; r < 4; r++) c[mi][ni][r] = 0.f;

    // loaders: thread -> row tid>>1, chunk pair (tid&1)*2 .. +1
    int lr = tid >> 1;
    int lc0 = (tid & 1) * 2;
    int bn = n0 + lr; if (bn > N - 1) bn = N - 1;
    const __half* Abase = A + (size_t)(m0 + lr) * K;
    const __half* Bbase = Bm + (size_t)bn * K;

#define SOFF(r, ch) ((r) * 32 + (((ch) ^ ((r) & 3)) << 3))

    // prologue: chunk 0 -> buf 0
#pragma unroll
    for (int c2 = 0; c2 < 2; c2++) {
        int ch = lc0 + c2;
        cp16(smaddr(&Asm[0][SOFF(lr, ch)]), Abase + ch * 8);
        cp16(smaddr(&Bsm[0][SOFF(lr, ch)]), Bbase + ch * 8);
    }
    asm volatile("cp.async.commit_group;");

    int buf = 0;
    for (int kc = 0; kc < K / 32; kc++) {
        asm volatile("cp.async.wait_group 0;");
        __syncthreads();
        if (kc + 1 < K / 32) {
            int kk = (kc + 1) * 32;
#pragma unroll
            for (int c2 = 0; c2 < 2; c2++) {
                int ch = lc0 + c2;
                cp16(smaddr(&Asm[buf ^ 1][SOFF(lr, ch)]), Abase + kk + ch * 8);
                cp16(smaddr(&Bsm[buf ^ 1][SOFF(lr, ch)]), Bbase + kk + ch * 8);
            }
            asm volatile("cp.async.commit_group;");
        }
#pragma unroll
        for (int ks = 0; ks < 2; ks++) {
            unsigned a[4][4], b[2][4];
#pragma unroll
            for (int mi = 0; mi < 4; mi++) {
                int row = wm * 64 + mi * 16 + (lane & 15);
                int ch  = ks * 2 + (lane >> 4);
                uint32_t ad = smaddr(&Asm[buf][SOFF(row, ch)]);
                asm volatile(
                    "ldmatrix.sync.aligned.m8n8.x4.shared.b16 {%0,%1,%2,%3}, [%4];"
                    : "=r"(a[mi][0]), "=r"(a[mi][1]), "=r"(a[mi][2]), "=r"(a[mi][3])
                    : "r"(ad));
            }
#pragma unroll
            for (int nj = 0; nj < 2; nj++) {
                int row = wn * 32 + nj * 16 + (lane & 7) + (lane >> 4) * 8;
                int ch  = ks * 2 + ((lane >> 3) & 1);
                uint32_t bd = smaddr(&Bsm[buf][SOFF(row, ch)]);
                asm volatile(
                    "ldmatrix.sync.aligned.m8n8.x4.shared.b16 {%0,%1,%2,%3}, [%4];"
                    : "=r"(b[nj][0]), "=r"(b[nj][1]), "=r"(b[nj][2]), "=r"(b[nj][3])
                    : "r"(bd));
            }
#pragma unroll
            for (int mi = 0; mi < 4; mi++)
#pragma unroll
                for (int ni = 0; ni < 4; ni++) {
                    unsigned bb0 = b[ni >> 1][(ni & 1) * 2];
                    unsigned bb1 = b[ni >> 1][(ni & 1) * 2 + 1];
                    asm volatile(
                        "mma.sync.aligned.m16n8k16.row.col.f32.f16.f16.f32 "
                        "{%0,%1,%2,%3}, {%4,%5,%6,%7}, {%8,%9}, {%0,%1,%2,%3};\n"
                        : "+f"(c[mi][ni][0]), "+f"(c[mi][ni][1]),
                          "+f"(c[mi][ni][2]), "+f"(c[mi][ni][3])
                        : "r"(a[mi][0]), "r"(a[mi][1]), "r"(a[mi][2]), "r"(a[mi][3]),
                          "r"(bb0), "r"(bb1));
                }
        }
        buf ^= 1;
    }

    int g = lane >> 2, q = lane & 3;
#pragma unroll
    for (int ni = 0; ni < 4; ni++) {
        int ncol = n0 + wn * 32 + ni * 8 + 2 * q;
        if (ncol >= N) continue;               // N even; pairs never split
        float b0 = bias[ncol], b1 = bias[ncol + 1];
#pragma unroll
        for (int mi = 0; mi < 4; mi++) {
            int r0 = m0 + wm * 64 + mi * 16 + g;
            *(float2*)(C + (size_t)r0 * N + ncol) =
                make_float2(c[mi][ni][0] + b0, c[mi][ni][1] + b1);
            *(float2*)(C + (size_t)(r0 + 8) * N + ncol) =
                make_float2(c[mi][ni][2] + b0, c[mi][ni][3] + b1);
        }
    }
#undef SOFF
}

// ---------------------------- GRU recurrence --------------------------------
// One block per (batch b, direction d).  384 threads: thread o owns gate
// output o = g*128 + j.  Whh row in registers as 64 packed f32x2; h read from
// smem as ulonglong2 so LDS.128 quads alias the f32x2 operands (no MOVs).
__global__ void __launch_bounds__(384, 1) recur_k(
    const float* __restrict__ GI,    // [B*T][768] or [B][768] (gi_const)
    const float* __restrict__ Whh,   // [2][384][128]
    const float* __restrict__ bhh,   // [2][384]
    float* __restrict__ Yf,          // fp32 outputs [B*T][256] or nullptr
    __half* __restrict__ Yh,         // fp16 outputs or nullptr
    float* __restrict__ Hout,        // [B][512]
    int loff, int gi_const)
{
    int b = blockIdx.x, d = blockIdx.y;
    int o = threadIdx.x;
    int g = o >> 7, j = o & 127;

    __shared__ __align__(16) float sh_h[128];
    __shared__ float rbuf[128];
    __shared__ float zbuf[128];

    unsigned long long w2[64];
    const float2* wrow = (const float2*)(Whh + ((size_t)(d * G3H + o)) * H_);
#pragma unroll
    for (int i = 0; i < 64; i++) {
        float2 v = wrow[i];
        w2[i] = pk2(v.x, v.y);
    }
    float bh = bhh[d * G3H + o];
    if (o < 128) sh_h[o] = 0.f;
    __syncthreads();

    float gi_c = gi_const ? GI[(size_t)b * 768 + d * G3H + o] : 0.f;

    for (int s = 0; s < T_; s++) {
        int t = d ? (T_ - 1 - s) : s;
        float gi = gi_const ? gi_c
                            : GI[((size_t)(b * T_ + t)) * 768 + d * G3H + o];
        unsigned long long acc0 = pk2(bh, 0.f);
        unsigned long long acc1 = 0ull;
        const ulonglong2* h2 = (const ulonglong2*)sh_h;
#pragma unroll
        for (int i = 0; i < 32; i++) {
            ulonglong2 v = h2[i];
            acc0 = f2fma(w2[2 * i],     v.x, acc0);
            acc1 = f2fma(w2[2 * i + 1], v.y, acc1);
        }
        float pa, pb, pc, pd;
        upk(acc0, pa, pb); upk(acc1, pc, pd);
        float gh = (pa + pc) + (pb + pd);     // h . Whh[o] + bhh[o]

        if (g == 0)      rbuf[j] = fast_sigm(gi + gh);
        else if (g == 1) zbuf[j] = fast_sigm(gi + gh);
        __syncthreads();
        if (g == 2) {
            float r = rbuf[j];
            float n = fast_tanh(gi + r * gh);
            float z = zbuf[j];
            float hn = (1.f - z) * n + z * sh_h[j];
            sh_h[j] = hn;
            int idx = (b * T_ + t) * 256 + d * 128 + j;
            if (Yf) Yf[idx] = hn;
            if (Yh) Yh[idx] = __float2half(hn);
        }
        __syncthreads();
    }
    if (g == 2) Hout[(size_t)b * 512 + loff + d * 128 + j] = sh_h[j];
}

// -------------------------------- fc head -----------------------------------
__global__ void fc_k(const float* __restrict__ ench,
                     const float* __restrict__ dech,
                     const float* __restrict__ W,
                     const float* __restrict__ bias,
                     float* __restrict__ out)
{
    int b = blockIdx.x;
    __shared__ float feat[1024];
    int tid = threadIdx.x;
    for (int i = tid; i < 512; i += 256) {
        feat[i]       = ench[b * 512 + i];
        feat[512 + i] = dech[b * 512 + i];
    }
    __syncthreads();
    int w = tid >> 5, lane = tid & 31;
    for (int c = w; c < NCLS; c += 8) {
        float acc = 0.f;
        for (int k = lane; k < 1024; k += 32)
            acc = fmaf(feat[k], W[c * 1024 + k], acc);
#pragma unroll
        for (int off = 16; off; off >>= 1)
            acc += __shfl_down_sync(0xffffffffu, acc, off);
        if (lane == 0) out[b * NCLS + c] = acc + bias[c];
    }
}

// ------------------------------- launcher -----------------------------------
extern "C" void kernel_launch(void* const* d_in, const int* in_sizes, int n_in,
                              void* d_out, int out_size)
{
    const void*  x    = d_in[0];
    const float* emb  = (const float*)d_in[1];
    const float* eWih0 = (const float*)d_in[2];
    const float* eWhh0 = (const float*)d_in[3];
    const float* ebih0 = (const float*)d_in[4];
    const float* ebhh0 = (const float*)d_in[5];
    const float* eWih1 = (const float*)d_in[6];
    const float* eWhh1 = (const float*)d_in[7];
    const float* ebih1 = (const float*)d_in[8];
    const float* ebhh1 = (const float*)d_in[9];
    const float* dWih0 = (const float*)d_in[10];
    const float* dWhh0 = (const float*)d_in[11];
    const float* dbih0 = (const float*)d_in[12];
    const float* dbhh0 = (const float*)d_in[13];
    const float* dWih1 = (const float*)d_in[14];
    const float* dWhh1 = (const float*)d_in[15];
    const float* dbih1 = (const float*)d_in[16];
    const float* dbhh1 = (const float*)d_in[17];
    const float* fcW   = (const float*)d_in[18];
    const float* fcb   = (const float*)d_in[19];
    const float* recW  = (const float*)d_in[20];
    const float* recb  = (const float*)d_in[21];

    float* out = (float*)d_out;          // [64,20]
    float* rec = out + B_ * NCLS;        // [64,100,10000]

    float *pE, *pGI, *pGIc, *pY0, *pench, *pdech;
    __half *pRECh, *pWh;
    cudaGetSymbolAddress((void**)&pE,    g_E);
    cudaGetSymbolAddress((void**)&pGI,   g_GI);
    cudaGetSymbolAddress((void**)&pGIc,  g_GIc);
    cudaGetSymbolAddress((void**)&pY0,   g_Y0);
    cudaGetSymbolAddress((void**)&pRECh, g_RECh);
    cudaGetSymbolAddress((void**)&pWh,   g_Wh);
    cudaGetSymbolAddress((void**)&pench, g_ench);
    cudaGetSymbolAddress((void**)&pdech, g_dech);

    detect_k<<<1, 64>>>((const unsigned int*)x);
    embed_k<<<(BT * 32 + 255) / 256, 256>>>(x, emb);

    // encoder layer 0
    gemm_bt_k<<<dim3(6, 50), 256>>>(pE, eWih0, ebih0, pGI, BT, 768, 128);
    recur_k<<<dim3(B_, 2), 384>>>(pGI, eWhh0, ebhh0, pY0, nullptr, pench, 0, 0);
    // encoder layer 1 (only final hidden needed)   [6th launch -> profiled]
    gemm_bt_k<<<dim3(6, 50), 256>>>(pY0, eWih1, ebih1, pGI, BT, 768, 256);
    recur_k<<<dim3(B_, 2), 384>>>(pGI, eWhh1, ebhh1, nullptr, nullptr, pench, 256, 0);
    // decoder layer 0 (broadcast input -> gi constant per step)
    gemm_bt_k<<<dim3(6, 1), 256>>>(pench, dWih0, dbih0, pGIc, B_, 768, 512);
    recur_k<<<dim3(B_, 2), 384>>>(pGIc, dWhh0, dbhh0, pY0, nullptr, pdech, 0, 1);
    // decoder layer 1 (outputs = rec_seq, written in fp16 for the HMMA GEMM)
    gemm_bt_k<<<dim3(6, 50), 256>>>(pY0, dWih1, dbih1, pGI, BT, 768, 256);
    recur_k<<<dim3(B_, 2), 384>>>(pGI, dWhh1, dbhh1, nullptr, pRECh, pdech, 256, 0);

    // heads
    cvt_k<<<(VOCAB * 128 + 255) / 256, 256>>>(recW, pWh, VOCAB * 128);
    fc_k<<<B_, 256>>>(pench, pdech, fcW, fcb, out);
    gemm_h_k<<<dim3((VOCAB + 127) / 128, BT / 128), 256>>>(
        pRECh, pWh, recb, rec, VOCAB);
}

// round 5
// speedup vs baseline: 2.9532x; 1.0528x over previous
#include <cuda_runtime.h>
#include <cuda_fp16.h>
#include <cstdint>

// ---------------------------------------------------------------------------
// FSNet: emb -> biGRU(2 layer) encoder -> broadcast -> biGRU(2 layer) decoder
//        -> fc head (64x20)  and  reconstruction GEMM (6400x10000x256)
// GRU path fp32 (f32x2 packed FMA). Reconstruction GEMM fp16 HMMA (fp32 acc)
// with cp.async double buffering + ldmatrix.
// ---------------------------------------------------------------------------

#define B_    64
#define T_    100
#define H_    128
#define G3H   384            // 3*H
#define BT    (B_*T_)        // 6400
#define VOCAB 10000
#define NCLS  20

// ------------------------------ scratch ------------------------------------
__device__ __align__(16) float  g_E   [BT * 128];     // embedded input
__device__ __align__(16) float  g_GI  [BT * 768];     // input-gate preacts
__device__ __align__(16) float  g_GIc [B_ * 768];     // dec layer0 const gi
__device__ __align__(16) float  g_Y0  [BT * 256];     // layer0 outputs
__device__ __align__(16) __half g_RECh[BT * 256];     // rec_seq in fp16
__device__ __align__(16) __half g_Wh  [VOCAB * 256];  // rec_W in fp16
__device__ __align__(16) float  g_ench[B_ * 512];
__device__ __align__(16) float  g_dech[B_ * 512];
__device__ int g_is32;

// --------------------------- helpers ---------------------------------------
__device__ __forceinline__ unsigned long long pk2(float x, float y) {
    unsigned long long r;
    asm("mov.b64 %0, {%1, %2};" : "=l"(r)
        : "r"(__float_as_uint(x)), "r"(__float_as_uint(y)));
    return r;
}
__device__ __forceinline__ void upk(unsigned long long v, float& x, float& y) {
    unsigned int a, b;
    asm("mov.b64 {%0, %1}, %2;" : "=r"(a), "=r"(b) : "l"(v));
    x = __uint_as_float(a); y = __uint_as_float(b);
}
__device__ __forceinline__ unsigned long long f2fma(unsigned long long a,
                                                    unsigned long long b,
                                                    unsigned long long c) {
    unsigned long long d;
    asm("fma.rn.f32x2 %0, %1, %2, %3;" : "=l"(d) : "l"(a), "l"(b), "l"(c));
    return d;
}
__device__ __forceinline__ float fast_sigm(float x) {
    float e;
    asm("ex2.approx.f32 %0, %1;" : "=f"(e) : "f"(-1.4426950408889634f * x));
    float r;
    asm("rcp.approx.f32 %0, %1;" : "=f"(r) : "f"(1.0f + e));
    return r;
}
__device__ __forceinline__ float fast_tanh(float x) {
    return 2.0f * fast_sigm(2.0f * x) - 1.0f;
}
__device__ __forceinline__ uint32_t smaddr(const void* p) {
    return (uint32_t)__cvta_generic_to_shared(p);
}
__device__ __forceinline__ void cp16(uint32_t dst, const void* src) {
    asm volatile("cp.async.cg.shared.global [%0], [%1], 16;"
                 :: "r"(dst), "l"(src));
}

// ------------------------- dtype detect (int32 vs int64) --------------------
__global__ void detect_k(const unsigned int* p) {
    __shared__ int s;
    if (threadIdx.x == 0) s = 0;
    __syncthreads();
    if (p[2 * threadIdx.x + 1] != 0) atomicOr(&s, 1);
    __syncthreads();
    if (threadIdx.x == 0) g_is32 = s;
}

// ------------------------------- embedding ----------------------------------
__global__ void embed_k(const void* xraw, const float* __restrict__ emb) {
    int s = blockIdx.x * blockDim.x + threadIdx.x;
    if (s >= BT * 32) return;
    int i = s >> 5, t = s & 31;
    long long xi;
    if (g_is32) xi = ((const int*)xraw)[i];
    else        xi = ((const long long*)xraw)[i];
    int r = (int)xi;
    if (r > 9999) r = 9999;
    if (r < 0)    r = 0;
    ((float4*)g_E)[s] = ((const float4*)emb)[r * 32 + t];
}

// -------------------------- fp32 -> fp16 convert ----------------------------
__global__ void cvt_k(const float* __restrict__ src, __half* __restrict__ dst,
                      int n2) {
    int i = blockIdx.x * blockDim.x + threadIdx.x;
    if (i >= n2) return;
    float2 v = ((const float2*)src)[i];
    ((__half2*)dst)[i] = __floats2half2_rn(v.x, v.y);
}

// ------------------------------ tiled fp32 GEMM -----------------------------
// C[M,N] = A[M,K] @ B[N,K]^T + bias[N].
#define BM 128
#define BN 128
#define BKt 16

__global__ void __launch_bounds__(256) gemm_bt_k(
    const float* __restrict__ A, const float* __restrict__ Bm,
    const float* __restrict__ bias, float* __restrict__ C,
    int M, int N, int K)
{
    __shared__ __align__(16) float As[BKt][BM + 4];
    __shared__ __align__(16) float Bs[BKt][BN + 4];
    int tid = threadIdx.x;
    int tx = tid & 15, ty = tid >> 4;
    int n0 = blockIdx.x * BN, m0 = blockIdx.y * BM;

    unsigned long long acc[4][8];
#pragma unroll
    for (int i = 0; i < 4; i++)
#pragma unroll
        for (int j = 0; j < 8; j++) acc[i][j] = 0ull;

    for (int kk = 0; kk < K; kk += BKt) {
#pragma unroll
        for (int q = 0; q < 2; q++) {
            int s = tid + q * 256;
            int row = s >> 2, kq = s & 3;
            float4 va = make_float4(0.f, 0.f, 0.f, 0.f);
            int gm = m0 + row;
            if (gm < M) va = *(const float4*)(A + (size_t)gm * K + kk + kq * 4);
            As[kq * 4 + 0][row] = va.x; As[kq * 4 + 1][row] = va.y;
            As[kq * 4 + 2][row] = va.z; As[kq * 4 + 3][row] = va.w;
            float4 vb = make_float4(0.f, 0.f, 0.f, 0.f);
            int gn = n0 + row;
            if (gn < N) vb = *(const float4*)(Bm + (size_t)gn * K + kk + kq * 4);
            Bs[kq * 4 + 0][row] = vb.x; Bs[kq * 4 + 1][row] = vb.y;
            Bs[kq * 4 + 2][row] = vb.z; Bs[kq * 4 + 3][row] = vb.w;
        }
        __syncthreads();
#pragma unroll
        for (int k = 0; k < BKt; k++) {
            const unsigned long long* ap =
                (const unsigned long long*)&As[k][ty * 8];
            unsigned long long a0 = ap[0], a1 = ap[1], a2 = ap[2], a3 = ap[3];
            float4 b0 = *(const float4*)&Bs[k][tx * 8];
            float4 b1 = *(const float4*)&Bs[k][tx * 8 + 4];
            float bv[8] = {b0.x, b0.y, b0.z, b0.w, b1.x, b1.y, b1.z, b1.w};
#pragma unroll
            for (int j = 0; j < 8; j++) {
                unsigned long long bd = pk2(bv[j], bv[j]);
                acc[0][j] = f2fma(a0, bd, acc[0][j]);
                acc[1][j] = f2fma(a1, bd, acc[1][j]);
                acc[2][j] = f2fma(a2, bd, acc[2][j]);
                acc[3][j] = f2fma(a3, bd, acc[3][j]);
            }
        }
        __syncthreads();
    }

    float bvv[8];
#pragma unroll
    for (int j = 0; j < 8; j++) {
        int gc = n0 + tx * 8 + j;
        bvv[j] = (gc < N) ? bias[gc] : 0.f;
    }
    int gc0 = n0 + tx * 8;
    bool c0ok = (gc0 < N), c1ok = (gc0 + 4 < N);
#pragma unroll
    for (int ip = 0; ip < 4; ip++) {
        float lo[8], hi[8];
#pragma unroll
        for (int j = 0; j < 8; j++) {
            upk(acc[ip][j], lo[j], hi[j]);
            lo[j] += bvv[j]; hi[j] += bvv[j];
        }
        int r0 = m0 + ty * 8 + 2 * ip;
        if (r0 < M) {
            float* cp = C + (size_t)r0 * N + gc0;
            if (c0ok) *(float4*)cp       = make_float4(lo[0], lo[1], lo[2], lo[3]);
            if (c1ok) *(float4*)(cp + 4) = make_float4(lo[4], lo[5], lo[6], lo[7]);
        }
        if (r0 + 1 < M) {
            float* cp = C + (size_t)(r0 + 1) * N + gc0;
            if (c0ok) *(float4*)cp       = make_float4(hi[0], hi[1], hi[2], hi[3]);
            if (c1ok) *(float4*)(cp + 4) = make_float4(hi[4], hi[5], hi[6], hi[7]);
        }
    }
}

// ----------------------- fp16 HMMA GEMM (rec head) --------------------------
// C[M=6400,N=10000] = A[M,256] @ B[N,256]^T + bias.
// Block 128x128, K-chunk 32 double-buffered (cp.async), 8 warps 2x4,
// warp tile 64x32, ldmatrix.x4 fragment loads from XOR-swizzled smem.
__global__ void __launch_bounds__(256, 2) gemm_h_k(
    const __half* __restrict__ A, const __half* __restrict__ Bm,
    const float* __restrict__ bias, float* __restrict__ C, int N)
{
    const int K = 256;
    __shared__ __align__(16) __half Asm[2][128 * 32];
    __shared__ __align__(16) __half Bsm[2][128 * 32];

    int tid = threadIdx.x, lane = tid & 31, wid = tid >> 5;
    int wm = wid & 1, wn = wid >> 1;
    int m0 = blockIdx.y * 128, n0 = blockIdx.x * 128;

    float c[4][4][4];
#pragma unroll
    for (int mi = 0; mi < 4; mi++)
#pragma unroll
        for (int ni = 0; ni < 4; ni++)
#pragma unroll
            for (int r = 0; r < 4; r++) c[mi][ni][r] = 0.f;

    int lr = tid >> 1;
    int lc0 = (tid & 1) * 2;
    int bn = n0 + lr; if (bn > N - 1) bn = N - 1;
    const __half* Abase = A + (size_t)(m0 + lr) * K;
    const __half* Bbase = Bm + (size_t)bn * K;

#define SOFF(r, ch) ((r) * 32 + (((ch) ^ ((r) & 3)) << 3))

#pragma unroll
    for (int c2 = 0; c2 < 2; c2++) {
        int ch = lc0 + c2;
        cp16(smaddr(&Asm[0][SOFF(lr, ch)]), Abase + ch * 8);
        cp16(smaddr(&Bsm[0][SOFF(lr, ch)]), Bbase + ch * 8);
    }
    asm volatile("cp.async.commit_group;");

    int buf = 0;
    for (int kc = 0; kc < K / 32; kc++) {
        asm volatile("cp.async.wait_group 0;");
        __syncthreads();
        if (kc + 1 < K / 32) {
            int kk = (kc + 1) * 32;
#pragma unroll
            for (int c2 = 0; c2 < 2; c2++) {
                int ch = lc0 + c2;
                cp16(smaddr(&Asm[buf ^ 1][SOFF(lr, ch)]), Abase + kk + ch * 8);
                cp16(smaddr(&Bsm[buf ^ 1][SOFF(lr, ch)]), Bbase + kk + ch * 8);
            }
            asm volatile("cp.async.commit_group;");
        }
#pragma unroll
        for (int ks = 0; ks < 2; ks++) {
            unsigned a[4][4], b[2][4];
#pragma unroll
            for (int mi = 0; mi < 4; mi++) {
                int row = wm * 64 + mi * 16 + (lane & 15);
                int ch  = ks * 2 + (lane >> 4);
                uint32_t ad = smaddr(&Asm[buf][SOFF(row, ch)]);
                asm volatile(
                    "ldmatrix.sync.aligned.m8n8.x4.shared.b16 {%0,%1,%2,%3}, [%4];"
                    : "=r"(a[mi][0]), "=r"(a[mi][1]), "=r"(a[mi][2]), "=r"(a[mi][3])
                    : "r"(ad));
            }
#pragma unroll
            for (int nj = 0; nj < 2; nj++) {
                int row = wn * 32 + nj * 16 + (lane & 7) + (lane >> 4) * 8;
                int ch  = ks * 2 + ((lane >> 3) & 1);
                uint32_t bd = smaddr(&Bsm[buf][SOFF(row, ch)]);
                asm volatile(
                    "ldmatrix.sync.aligned.m8n8.x4.shared.b16 {%0,%1,%2,%3}, [%4];"
                    : "=r"(b[nj][0]), "=r"(b[nj][1]), "=r"(b[nj][2]), "=r"(b[nj][3])
                    : "r"(bd));
            }
#pragma unroll
            for (int mi = 0; mi < 4; mi++)
#pragma unroll
                for (int ni = 0; ni < 4; ni++) {
                    unsigned bb0 = b[ni >> 1][(ni & 1) * 2];
                    unsigned bb1 = b[ni >> 1][(ni & 1) * 2 + 1];
                    asm volatile(
                        "mma.sync.aligned.m16n8k16.row.col.f32.f16.f16.f32 "
                        "{%0,%1,%2,%3}, {%4,%5,%6,%7}, {%8,%9}, {%0,%1,%2,%3};\n"
                        : "+f"(c[mi][ni][0]), "+f"(c[mi][ni][1]),
                          "+f"(c[mi][ni][2]), "+f"(c[mi][ni][3])
                        : "r"(a[mi][0]), "r"(a[mi][1]), "r"(a[mi][2]), "r"(a[mi][3]),
                          "r"(bb0), "r"(bb1));
                }
        }
        buf ^= 1;
    }

    int g = lane >> 2, q = lane & 3;
#pragma unroll
    for (int ni = 0; ni < 4; ni++) {
        int ncol = n0 + wn * 32 + ni * 8 + 2 * q;
        if (ncol >= N) continue;
        float b0 = bias[ncol], b1 = bias[ncol + 1];
#pragma unroll
        for (int mi = 0; mi < 4; mi++) {
            int r0 = m0 + wm * 64 + mi * 16 + g;
            *(float2*)(C + (size_t)r0 * N + ncol) =
                make_float2(c[mi][ni][0] + b0, c[mi][ni][1] + b1);
            *(float2*)(C + (size_t)(r0 + 8) * N + ncol) =
                make_float2(c[mi][ni][2] + b0, c[mi][ni][3] + b1);
        }
    }
#undef SOFF
}

// ---------------------------- GRU recurrence --------------------------------
// One block per (batch b, direction d).  384 threads.
// Role map:  warps 0-7: lanes 0-15 -> gate r of j = wid*16+lane,
//                       lanes 16-31 -> gate n of j = wid*16+(lane-16)
//            warps 8-11: gate z of j = (wid-8)*32+lane.
// r -> n delivered by shfl.xor(16) (same warp).  z via smem zbuf.
// gi for step s+1 prefetched during step s (hides the LDG).
__global__ void __launch_bounds__(384, 1) recur_k(
    const float* __restrict__ GI,    // [B*T][768] or [B][768] (gi_const)
    const float* __restrict__ Whh,   // [2][384][128]
    const float* __restrict__ bhh,   // [2][384]
    float* __restrict__ Yf,          // fp32 outputs [B*T][256] or nullptr
    __half* __restrict__ Yh,         // fp16 outputs or nullptr
    float* __restrict__ Hout,        // [B][512]
    int loff, int gi_const)
{
    int b = blockIdx.x, d = blockIdx.y;
    int o = threadIdx.x;
    int wid = o >> 5, lane = o & 31;

    int gate, j;
    if (wid < 8) {
        gate = (lane < 16) ? 0 : 2;
        j = wid * 16 + (lane & 15);
    } else {
        gate = 1;
        j = (wid - 8) * 32 + lane;
    }
    int row = gate * H_ + j;               // 0..383
    bool is_n = (gate == 2);

    __shared__ __align__(16) float sh_h[128];
    __shared__ float zbuf[128];

    unsigned long long w2[64];
    const float2* wrow = (const float2*)(Whh + ((size_t)(d * G3H + row)) * H_);
#pragma unroll
    for (int i = 0; i < 64; i++) {
        float2 v = wrow[i];
        w2[i] = pk2(v.x, v.y);
    }
    float bh = bhh[d * G3H + row];
    if (o < 128) sh_h[o] = 0.f;
    __syncthreads();

    // prefetch gi for step 0
    float gi_next;
    if (gi_const) {
        gi_next = GI[(size_t)b * 768 + d * G3H + row];
    } else {
        int t0 = d ? (T_ - 1) : 0;
        gi_next = GI[((size_t)(b * T_ + t0)) * 768 + d * G3H + row];
    }

    for (int s = 0; s < T_; s++) {
        int t = d ? (T_ - 1 - s) : s;
        float gi = gi_next;
        if (!gi_const && s + 1 < T_) {
            int t1 = d ? (T_ - 2 - s) : (s + 1);
            gi_next = GI[((size_t)(b * T_ + t1)) * 768 + d * G3H + row];
        }

        unsigned long long acc0 = pk2(bh, 0.f);
        unsigned long long acc1 = 0ull, acc2 = 0ull, acc3 = 0ull;
        const ulonglong2* h2 = (const ulonglong2*)sh_h;
#pragma unroll
        for (int i = 0; i < 16; i++) {
            ulonglong2 va = h2[2 * i];
            ulonglong2 vb = h2[2 * i + 1];
            acc0 = f2fma(w2[4 * i + 0], va.x, acc0);
            acc1 = f2fma(w2[4 * i + 1], va.y, acc1);
            acc2 = f2fma(w2[4 * i + 2], vb.x, acc2);
            acc3 = f2fma(w2[4 * i + 3], vb.y, acc3);
        }
        acc0 = pk2(0.f, 0.f) == 0 ? acc0 : acc0;  // no-op keep
        float p0, p1, p2, p3, p4, p5, p6, p7;
        upk(acc0, p0, p1); upk(acc1, p2, p3);
        upk(acc2, p4, p5); upk(acc3, p6, p7);
        float gh = ((p0 + p2) + (p4 + p6)) + ((p1 + p3) + (p5 + p7));

        float hold = sh_h[j];                // old h (needed by n threads)

        float rv = 0.f;
        if (!is_n) {
            float a = fast_sigm(gi + gh);
            if (gate == 0) rv = a;           // r: keep in register for shfl
            else           zbuf[j] = a;      // z: publish before barrier
        }
        float rx = __shfl_xor_sync(0xffffffffu, rv, 16);  // r -> n lanes

        __syncthreads();                     // zbuf visible; h reads done

        if (is_n) {
            float n = fast_tanh(gi + rx * gh);
            float z = zbuf[j];
            float hn = (1.f - z) * n + z * hold;
            sh_h[j] = hn;
            int idx = (b * T_ + t) * 256 + d * H_ + j;
            if (Yf) Yf[idx] = hn;
            if (Yh) Yh[idx] = __float2half(hn);
        }
        __syncthreads();
    }
    if (is_n) Hout[(size_t)b * 512 + loff + d * H_ + j] = sh_h[j];
}

// -------------------------------- fc head -----------------------------------
__global__ void fc_k(const float* __restrict__ ench,
                     const float* __restrict__ dech,
                     const float* __restrict__ W,
                     const float* __restrict__ bias,
                     float* __restrict__ out)
{
    int b = blockIdx.x;
    __shared__ float feat[1024];
    int tid = threadIdx.x;
    for (int i = tid; i < 512; i += 256) {
        feat[i]       = ench[b * 512 + i];
        feat[512 + i] = dech[b * 512 + i];
    }
    __syncthreads();
    int w = tid >> 5, lane = tid & 31;
    for (int c = w; c < NCLS; c += 8) {
        float acc = 0.f;
        for (int k = lane; k < 1024; k += 32)
            acc = fmaf(feat[k], W[c * 1024 + k], acc);
#pragma unroll
        for (int off = 16; off; off >>= 1)
            acc += __shfl_down_sync(0xffffffffu, acc, off);
        if (lane == 0) out[b * NCLS + c] = acc + bias[c];
    }
}

// ------------------------------- launcher -----------------------------------
extern "C" void kernel_launch(void* const* d_in, const int* in_sizes, int n_in,
                              void* d_out, int out_size)
{
    const void*  x    = d_in[0];
    const float* emb  = (const float*)d_in[1];
    const float* eWih0 = (const float*)d_in[2];
    const float* eWhh0 = (const float*)d_in[3];
    const float* ebih0 = (const float*)d_in[4];
    const float* ebhh0 = (const float*)d_in[5];
    const float* eWih1 = (const float*)d_in[6];
    const float* eWhh1 = (const float*)d_in[7];
    const float* ebih1 = (const float*)d_in[8];
    const float* ebhh1 = (const float*)d_in[9];
    const float* dWih0 = (const float*)d_in[10];
    const float* dWhh0 = (const float*)d_in[11];
    const float* dbih0 = (const float*)d_in[12];
    const float* dbhh0 = (const float*)d_in[13];
    const float* dWih1 = (const float*)d_in[14];
    const float* dWhh1 = (const float*)d_in[15];
    const float* dbih1 = (const float*)d_in[16];
    const float* dbhh1 = (const float*)d_in[17];
    const float* fcW   = (const float*)d_in[18];
    const float* fcb   = (const float*)d_in[19];
    const float* recW  = (const float*)d_in[20];
    const float* recb  = (const float*)d_in[21];

    float* out = (float*)d_out;          // [64,20]
    float* rec = out + B_ * NCLS;        // [64,100,10000]

    float *pE, *pGI, *pGIc, *pY0, *pench, *pdech;
    __half *pRECh, *pWh;
    cudaGetSymbolAddress((void**)&pE,    g_E);
    cudaGetSymbolAddress((void**)&pGI,   g_GI);
    cudaGetSymbolAddress((void**)&pGIc,  g_GIc);
    cudaGetSymbolAddress((void**)&pY0,   g_Y0);
    cudaGetSymbolAddress((void**)&pRECh, g_RECh);
    cudaGetSymbolAddress((void**)&pWh,   g_Wh);
    cudaGetSymbolAddress((void**)&pench, g_ench);
    cudaGetSymbolAddress((void**)&pdech, g_dech);

    detect_k<<<1, 64>>>((const unsigned int*)x);
    embed_k<<<(BT * 32 + 255) / 256, 256>>>(x, emb);

    // encoder layer 0
    gemm_bt_k<<<dim3(6, 50), 256>>>(pE, eWih0, ebih0, pGI, BT, 768, 128);
    recur_k<<<dim3(B_, 2), 384>>>(pGI, eWhh0, ebhh0, pY0, nullptr, pench, 0, 0);
    // encoder layer 1 (only final hidden needed)   [6th launch -> profiled]
    gemm_bt_k<<<dim3(6, 50), 256>>>(pY0, eWih1, ebih1, pGI, BT, 768, 256);
    recur_k<<<dim3(B_, 2), 384>>>(pGI, eWhh1, ebhh1, nullptr, nullptr, pench, 256, 0);
    // decoder layer 0 (broadcast input -> gi constant per step)
    gemm_bt_k<<<dim3(6, 1), 256>>>(pench, dWih0, dbih0, pGIc, B_, 768, 512);
    recur_k<<<dim3(B_, 2), 384>>>(pGIc, dWhh0, dbhh0, pY0, nullptr, pdech, 0, 1);
    // decoder layer 1 (outputs = rec_seq, written in fp16 for the HMMA GEMM)
    gemm_bt_k<<<dim3(6, 50), 256>>>(pY0, dWih1, dbih1, pGI, BT, 768, 256);
    recur_k<<<dim3(B_, 2), 384>>>(pGI, dWhh1, dbhh1, nullptr, pRECh, pdech, 256, 0);

    // heads
    cvt_k<<<(VOCAB * 128 + 255) / 256, 256>>>(recW, pWh, VOCAB * 128);
    fc_k<<<B_, 256>>>(pench, pdech, fcW, fcb, out);
    gemm_h_k<<<dim3((VOCAB + 127) / 128, BT / 128), 256>>>(
        pRECh, pWh, recb, rec, VOCAB);
}